// round 7
// baseline (speedup 1.0000x reference)
#include <cuda_runtime.h>
#include <cuda_fp16.h>

#define NN 100000
#define EE 1000000
#define HH 64
#define GG 64
#define BN_EPS 1e-5f

// ---------------- scratch (static __device__, no allocations) ----------------
__device__ int      g_deg[NN];        // in-degree (excluding self loop)
__device__ int      g_off[NN];        // CSR offsets; after scatter: END offsets
__device__ int      g_csr[EE];        // CSR src row per incoming edge, bucketed by dst
__device__ float    g_dinv[NN];       // rsqrt(deg+1)
__device__ __half2  g_hs[NN * 32];    // layer-1 transformed+scaled features (fp16)
__device__ __half2  g_hs2[NN * 32];   // layer-2 transformed+scaled features (fp16)
__device__ float    g_pool[GG * 64];  // pooled sums
__device__ int      g_gstart[GG + 1]; // graph segment starts
__device__ int      g_bsum[64];       // scan block sums
__device__ unsigned g_wfrag[2][2048]; // preformatted W fragments (half2 words), both layers

// ---------------- init: zero counters/pool, graph bounds, W fragment preformat ----------------
__global__ void k_zero(const int* __restrict__ batch,
                       const float* __restrict__ W1, const float* __restrict__ W2) {
    int i = blockIdx.x * blockDim.x + threadIdx.x;
    if (i < NN) g_deg[i] = 0;
    if (i < GG * 64) g_pool[i] = 0.f;
    if (i < 4096) {
        int l = i >> 11;
        int o = i & 2047;
        const float* W = l ? W2 : W1;
        int reg = o & 1, lane = (o >> 1) & 31, nt = (o >> 6) & 7, ktp = o >> 9;
        int n = nt * 8 + (lane >> 2);
        int k = ktp * 16 + reg * 8 + (lane & 3) * 2;
        __half2 h = __floats2half2_rn(W[n * 64 + k], W[n * 64 + k + 1]);
        g_wfrag[l][o] = *(unsigned*)&h;
    }
    if (i <= NN) {
        int prev = (i == 0) ? -1 : batch[i - 1];
        int cur  = (i < NN) ? batch[i] : GG;
        for (int g = prev + 1; g <= cur && g <= GG; g++) g_gstart[g] = i;
    }
}

// ---------------- degree histogram (4 edges/thread) ----------------
__global__ void k_degree(const int* __restrict__ ei) {
    int e = blockIdx.x * blockDim.x + threadIdx.x;
    if (e >= EE / 4) return;
    int4 c = ((const int4*)(ei + EE))[e];
    atomicAdd(&g_deg[c.x], 1);
    atomicAdd(&g_deg[c.y], 1);
    atomicAdd(&g_deg[c.z], 1);
    atomicAdd(&g_deg[c.w], 1);
}

// ---------------- scan stage A ----------------
__global__ void k_scan_a() {
    __shared__ int sh[256];
    int t = threadIdx.x;
    int base = blockIdx.x * 2048 + t * 8;
    int vals[8];
    int ts = 0;
#pragma unroll
    for (int j = 0; j < 8; j++) {
        int idx = base + j;
        vals[j] = (idx < NN) ? g_deg[idx] : 0;
        if (idx < NN) g_dinv[idx] = rsqrtf((float)(vals[j] + 1));
        ts += vals[j];
    }
    sh[t] = ts;
    __syncthreads();
#pragma unroll
    for (int d = 1; d < 256; d <<= 1) {
        int v = (t >= d) ? sh[t - d] : 0;
        __syncthreads();
        sh[t] += v;
        __syncthreads();
    }
    int excl = sh[t] - ts;
    int run = 0;
#pragma unroll
    for (int j = 0; j < 8; j++) {
        int idx = base + j;
        if (idx < NN) g_off[idx] = excl + run;
        run += vals[j];
    }
    if (t == 255) g_bsum[blockIdx.x] = sh[255];
}

// ---------------- scan stage C ----------------
__global__ void k_scan_c() {
    __shared__ int sv[64];
    __shared__ int pre;
    int t = threadIdx.x;
    int c = blockIdx.x >> 3;
    if (t < 64) sv[t] = (t < c) ? g_bsum[t] : 0;
    __syncthreads();
    if (t < 32) {
        int v = sv[t] + sv[t + 32];
#pragma unroll
        for (int d = 16; d > 0; d >>= 1) v += __shfl_down_sync(0xFFFFFFFFu, v, d);
        if (t == 0) pre = v;
    }
    __syncthreads();
    int i = blockIdx.x * 256 + t;
    if (i < NN) g_off[i] += pre;
}

// ---------------- CSR scatter (4 edges/thread) ----------------
__global__ void k_scatter(const int* __restrict__ ei) {
    int e = blockIdx.x * blockDim.x + threadIdx.x;
    if (e >= EE / 4) return;
    int4 r = ((const int4*)ei)[e];
    int4 c = ((const int4*)(ei + EE))[e];
    g_csr[atomicAdd(&g_off[c.x], 1)] = r.x;
    g_csr[atomicAdd(&g_off[c.y], 1)] = r.y;
    g_csr[atomicAdd(&g_off[c.z], 1)] = r.z;
    g_csr[atomicAdd(&g_off[c.w], 1)] = r.w;
}

// ---------------- layer-1 GEMM: 128 rows/block, m16n8k16 fp16 MMA ----------------
// hs[v,:] = fp16( (X[v,:] @ W1^T) * dinv[v] )
__global__ void __launch_bounds__(128) k_gemm_mma(
    const float4* __restrict__ X4, const unsigned* __restrict__ wfrag,
    __half2* __restrict__ O) {
    __shared__ unsigned sA[8][4][32][4];   // 16KB: [tile][ktp][lane][reg]
    __shared__ unsigned sB[2048];          // 8KB
    int tid = threadIdx.x;
    int base = blockIdx.x * 128;

#pragma unroll
    for (int i = tid; i < 512; i += 128)
        ((uint4*)sB)[i] = ((const uint4*)wfrag)[i];

    for (int i = tid; i < 2048; i += 128) {
        int r = i >> 4, j = i & 15;
        int R = base + r;
        float4 v = make_float4(0.f, 0.f, 0.f, 0.f);
        if (R < NN) v = X4[(size_t)R * 16 + j];
        int w8 = r >> 4, rr = r & 15;
        int ktp = j >> 2, jj = j & 3;
        int reg = ((rr >> 3) & 1) | ((jj >> 1) << 1);
        int t0 = (2 * jj) & 3;
        int lb = (rr & 7) * 4;
        __half2 h0 = __floats2half2_rn(v.x, v.y);
        __half2 h1 = __floats2half2_rn(v.z, v.w);
        sA[w8][ktp][lb + t0][reg]     = *(unsigned*)&h0;
        sA[w8][ktp][lb + t0 + 1][reg] = *(unsigned*)&h1;
    }
    __syncthreads();

    int lane = tid & 31;
    int w = tid >> 5;
    float d0[8][4], d1[8][4];
#pragma unroll
    for (int nt = 0; nt < 8; nt++)
#pragma unroll
        for (int j = 0; j < 4; j++) { d0[nt][j] = 0.f; d1[nt][j] = 0.f; }

#pragma unroll
    for (int ktp = 0; ktp < 4; ktp++) {
        uint4 aA = *(const uint4*)&sA[w][ktp][lane][0];
        uint4 aB = *(const uint4*)&sA[w + 4][ktp][lane][0];
#pragma unroll
        for (int nt = 0; nt < 8; nt++) {
            uint2 b = *(const uint2*)&sB[(((ktp << 3) + nt) << 6) + (lane << 1)];
            asm volatile(
                "mma.sync.aligned.m16n8k16.row.col.f32.f16.f16.f32 "
                "{%0,%1,%2,%3}, {%4,%5,%6,%7}, {%8,%9}, {%0,%1,%2,%3};"
                : "+f"(d0[nt][0]), "+f"(d0[nt][1]), "+f"(d0[nt][2]), "+f"(d0[nt][3])
                : "r"(aA.x), "r"(aA.y), "r"(aA.z), "r"(aA.w), "r"(b.x), "r"(b.y));
            asm volatile(
                "mma.sync.aligned.m16n8k16.row.col.f32.f16.f16.f32 "
                "{%0,%1,%2,%3}, {%4,%5,%6,%7}, {%8,%9}, {%0,%1,%2,%3};"
                : "+f"(d1[nt][0]), "+f"(d1[nt][1]), "+f"(d1[nt][2]), "+f"(d1[nt][3])
                : "r"(aB.x), "r"(aB.y), "r"(aB.z), "r"(aB.w), "r"(b.x), "r"(b.y));
        }
    }

    int g = lane >> 2, t4 = lane & 3;
#pragma unroll
    for (int t2 = 0; t2 < 2; t2++) {
        float (*d)[4] = t2 ? d1 : d0;
        int row0 = base + t2 * 64 + w * 16 + g;
        int row1 = row0 + 8;
        bool v0 = row0 < NN, v1 = row1 < NN;
        float dv0 = v0 ? g_dinv[row0] : 0.f;
        float dv1 = v1 ? g_dinv[row1] : 0.f;
#pragma unroll
        for (int nt = 0; nt < 8; nt++) {
            int cp = nt * 4 + t4;
            if (v0) O[(size_t)row0 * 32 + cp] = __floats2half2_rn(d[nt][0] * dv0, d[nt][1] * dv0);
            if (v1) O[(size_t)row1 * 32 + cp] = __floats2half2_rn(d[nt][2] * dv1, d[nt][3] * dv1);
        }
    }
}

// ---------------- FUSED: agg1 + bias + BN + ReLU + gemm2 + dinv -> hs2 ----------------
// Block: 128 thr / 4 warps / 64 nodes. Warp w aggregates nodes 16w..16w+15,
// stages results directly as fp16 A-fragments, then MMA with W2 fragments.
__global__ void __launch_bounds__(128) k_agg_gemm(
    const __half2* __restrict__ hs, const unsigned* __restrict__ wfrag,
    __half2* __restrict__ O,
    const float* __restrict__ bias,
    const float* __restrict__ bng, const float* __restrict__ bnb,
    const float* __restrict__ bnm, const float* __restrict__ bnv) {
    __shared__ unsigned sA[4][4][32][4];   // 8KB
    __shared__ unsigned sB[2048];          // 8KB
    int tid = threadIdx.x;
    int base = blockIdx.x * 64;
    int lane = tid & 31;
    int w = tid >> 5;

#pragma unroll
    for (int i = tid; i < 512; i += 128)
        ((uint4*)sB)[i] = ((const uint4*)wfrag)[i];

    // per-lane channel constants (channels 2l, 2l+1)
    int c = 2 * lane;
    float bx = bias[c], by = bias[c + 1];
    float sx = bng[c] * rsqrtf(bnv[c] + BN_EPS);
    float sy = bng[c + 1] * rsqrtf(bnv[c + 1] + BN_EPS);
    float mx = bnm[c], my = bnm[c + 1];
    float ax = bnb[c], ay = bnb[c + 1];

    // fragment store target for kpair index = lane (per node n)
    int ktp = lane >> 3;
    int regHalf = (lane >> 2) & 1;  // kpair-local >= 4
    int laneLow = lane & 3;

    for (int n = 0; n < 16; n++) {
        int node = base + w * 16 + n;
        unsigned hval = 0;
        if (node < NN) {
            float2 acc = __half22float2(hs[(size_t)node * 32 + lane]);  // self loop
            int e = g_off[node];
            int cnt = g_deg[node];
            int s = e - cnt;
            int i = 0;
            for (; i + 4 <= cnt; i += 4) {
                int r0 = g_csr[s + i + 0];
                int r1 = g_csr[s + i + 1];
                int r2 = g_csr[s + i + 2];
                int r3 = g_csr[s + i + 3];
                float2 a0 = __half22float2(hs[(size_t)r0 * 32 + lane]);
                float2 a1 = __half22float2(hs[(size_t)r1 * 32 + lane]);
                float2 a2 = __half22float2(hs[(size_t)r2 * 32 + lane]);
                float2 a3 = __half22float2(hs[(size_t)r3 * 32 + lane]);
                acc.x += (a0.x + a1.x) + (a2.x + a3.x);
                acc.y += (a0.y + a1.y) + (a2.y + a3.y);
            }
            for (; i < cnt; i++) {
                float2 a = __half22float2(hs[(size_t)g_csr[s + i] * 32 + lane]);
                acc.x += a.x;
                acc.y += a.y;
            }
            float dv = g_dinv[node];
            float px = fmaf(acc.x, dv, bx);
            float py = fmaf(acc.y, dv, by);
            float ox = fmaxf(0.f, fmaf(px - mx, sx, ax));
            float oy = fmaxf(0.f, fmaf(py - my, sy, ay));
            __half2 h = __floats2half2_rn(ox, oy);
            hval = *(unsigned*)&h;
        }
        int reg = ((n >> 3) & 1) | (regHalf << 1);
        sA[w][ktp][(n & 7) * 4 + laneLow][reg] = hval;
    }
    __syncthreads();

    float d[8][4];
#pragma unroll
    for (int nt = 0; nt < 8; nt++)
#pragma unroll
        for (int j = 0; j < 4; j++) d[nt][j] = 0.f;

#pragma unroll
    for (int kt = 0; kt < 4; kt++) {
        uint4 a = *(const uint4*)&sA[w][kt][lane][0];
#pragma unroll
        for (int nt = 0; nt < 8; nt++) {
            uint2 b = *(const uint2*)&sB[(((kt << 3) + nt) << 6) + (lane << 1)];
            asm volatile(
                "mma.sync.aligned.m16n8k16.row.col.f32.f16.f16.f32 "
                "{%0,%1,%2,%3}, {%4,%5,%6,%7}, {%8,%9}, {%0,%1,%2,%3};"
                : "+f"(d[nt][0]), "+f"(d[nt][1]), "+f"(d[nt][2]), "+f"(d[nt][3])
                : "r"(a.x), "r"(a.y), "r"(a.z), "r"(a.w), "r"(b.x), "r"(b.y));
        }
    }

    int g = lane >> 2, t4 = lane & 3;
    int row0 = base + w * 16 + g;
    int row1 = row0 + 8;
    bool v0 = row0 < NN, v1 = row1 < NN;
    float dv0 = v0 ? g_dinv[row0] : 0.f;
    float dv1 = v1 ? g_dinv[row1] : 0.f;
#pragma unroll
    for (int nt = 0; nt < 8; nt++) {
        int cp = nt * 4 + t4;
        if (v0) O[(size_t)row0 * 32 + cp] = __floats2half2_rn(d[nt][0] * dv0, d[nt][1] * dv0);
        if (v1) O[(size_t)row1 * 32 + cp] = __floats2half2_rn(d[nt][2] * dv1, d[nt][3] * dv1);
    }
}

// ---------------- agg2 + bias + BN + ReLU + fused pooling ----------------
template <int NODES_PER_BLK>
__global__ void k_agg_pool(const __half2* __restrict__ hs,
                           const int* __restrict__ batch,
                           const float* __restrict__ bias,
                           const float* __restrict__ bng, const float* __restrict__ bnb,
                           const float* __restrict__ bnm, const float* __restrict__ bnv) {
    __shared__ float sp[2][64];
    int t = threadIdx.x;
    int w0 = blockIdx.x * NODES_PER_BLK;
    if (t < 128) sp[t >> 6][t & 63] = 0.f;
    int gid0 = batch[w0];
    int wl = w0 + NODES_PER_BLK - 1;
    int gidL = batch[wl < NN ? wl : NN - 1];
    __syncthreads();

    int w = w0 + (t >> 5);
    int l = t & 31;
    if (w < NN) {
        float2 acc = __half22float2(hs[(size_t)w * 32 + l]);  // self loop
        int e = g_off[w];
        int cnt = g_deg[w];
        int s = e - cnt;
        int i = 0;
        for (; i + 4 <= cnt; i += 4) {
            int r0 = g_csr[s + i + 0];
            int r1 = g_csr[s + i + 1];
            int r2 = g_csr[s + i + 2];
            int r3 = g_csr[s + i + 3];
            float2 a0 = __half22float2(hs[(size_t)r0 * 32 + l]);
            float2 a1 = __half22float2(hs[(size_t)r1 * 32 + l]);
            float2 a2 = __half22float2(hs[(size_t)r2 * 32 + l]);
            float2 a3 = __half22float2(hs[(size_t)r3 * 32 + l]);
            acc.x += (a0.x + a1.x) + (a2.x + a3.x);
            acc.y += (a0.y + a1.y) + (a2.y + a3.y);
        }
        for (; i < cnt; i++) {
            float2 a = __half22float2(hs[(size_t)g_csr[s + i] * 32 + l]);
            acc.x += a.x;
            acc.y += a.y;
        }
        float dv = g_dinv[w];
        int c = 2 * l;
        float px = fmaf(acc.x, dv, bias[c]);
        float py = fmaf(acc.y, dv, bias[c + 1]);
        float sx = bng[c] * rsqrtf(bnv[c] + BN_EPS);
        float sy = bng[c + 1] * rsqrtf(bnv[c + 1] + BN_EPS);
        float ox = fmaxf(0.f, fmaf(px - bnm[c], sx, bnb[c]));
        float oy = fmaxf(0.f, fmaf(py - bnm[c + 1], sy, bnb[c + 1]));
        int gid = batch[w];
        int slot = gid - gid0;
        if (slot < 2) {
            atomicAdd(&sp[slot][c], ox);
            atomicAdd(&sp[slot][c + 1], oy);
        } else {
            atomicAdd(&g_pool[gid * 64 + c], ox);
            atomicAdd(&g_pool[gid * 64 + c + 1], oy);
        }
    }
    __syncthreads();
    if (t < 128) {
        int s = t >> 6, ch = t & 63;
        int gg = gid0 + s;
        if (gg <= gidL && gg < GG) atomicAdd(&g_pool[gg * 64 + ch], sp[s][ch]);
    }
}

// ---------------- MLP head ----------------
__global__ void k_head(const float* __restrict__ l1W, const float* __restrict__ l1b,
                       const float* __restrict__ l2W, const float* __restrict__ l2b,
                       float* __restrict__ out) {
    __shared__ float sW1[32 * 64];
    __shared__ float sW2[32];
    __shared__ float sB1[32];
    int t = threadIdx.x;  // 64 threads
    for (int i = t; i < 2048; i += 64) sW1[i] = l1W[i];
    if (t < 32) { sW2[t] = l2W[t]; sB1[t] = l1b[t]; }
    __syncthreads();
    if (t >= GG) return;
    int g = t;
    int cnt = g_gstart[g + 1] - g_gstart[g];
    float inv = 1.f / fmaxf((float)cnt, 1.f);
    float p[64];
#pragma unroll
    for (int k = 0; k < 64; k++) p[k] = g_pool[g * 64 + k] * inv;
    float o = l2b[0];
#pragma unroll 4
    for (int j = 0; j < 32; j++) {
        float hsum = sB1[j];
#pragma unroll
        for (int k = 0; k < 64; k++) hsum = fmaf(p[k], sW1[j * 64 + k], hsum);
        o = fmaf(fmaxf(hsum, 0.f), sW2[j], o);
    }
    out[g] = o;
}

// ---------------- launch ----------------
extern "C" void kernel_launch(void* const* d_in, const int* in_sizes, int n_in,
                              void* d_out, int out_size) {
    const float* x      = (const float*)d_in[0];
    const int*   ei     = (const int*)d_in[1];
    const int*   batch  = (const int*)d_in[2];
    const float* W1     = (const float*)d_in[3];
    const float* b1     = (const float*)d_in[4];
    const float* W2     = (const float*)d_in[5];
    const float* b2     = (const float*)d_in[6];
    const float* bn1g   = (const float*)d_in[7];
    const float* bn1b   = (const float*)d_in[8];
    const float* bn1m   = (const float*)d_in[9];
    const float* bn1v   = (const float*)d_in[10];
    const float* bn2g   = (const float*)d_in[11];
    const float* bn2b   = (const float*)d_in[12];
    const float* bn2m   = (const float*)d_in[13];
    const float* bn2v   = (const float*)d_in[14];
    const float* l1W    = (const float*)d_in[15];
    const float* l1b    = (const float*)d_in[16];
    const float* l2W    = (const float*)d_in[17];
    const float* l2b    = (const float*)d_in[18];
    float* out = (float*)d_out;

    __half2 *hs, *hs2;
    unsigned* wfrag;
    cudaGetSymbolAddress((void**)&hs, g_hs);
    cudaGetSymbolAddress((void**)&hs2, g_hs2);
    cudaGetSymbolAddress((void**)&wfrag, g_wfrag);

    const int TB = 256;
    int nb_e4 = (EE / 4 + TB - 1) / TB;
    int nb_scan = (NN + 2047) / 2048;    // 49
    int nb_g1 = (NN + 127) / 128;        // 782
    int nb_f  = (NN + 63) / 64;          // 1563

    k_zero<<<(NN + 1 + TB - 1) / TB, TB>>>(batch, W1, W2);          // 0
    k_degree<<<nb_e4, TB>>>(ei);                                     // 1
    k_scan_a<<<nb_scan, 256>>>();                                    // 2
    k_gemm_mma<<<nb_g1, 128>>>((const float4*)x, wfrag, hs);         // 3  <- ncu capture
    k_scan_c<<<(NN + 255) / 256, 256>>>();                           // 4
    k_scatter<<<nb_e4, TB>>>(ei);                                    // 5

    // fused: agg1 + BN1 + ReLU + gemm2 + dinv -> hs2
    k_agg_gemm<<<nb_f, 128>>>(hs, wfrag + 2048, hs2, b1, bn1g, bn1b, bn1m, bn1v);  // 6
    // agg2 + BN2 + ReLU + pooling
    k_agg_pool<16><<<NN / 16, 512>>>(hs2, batch, b2, bn2g, bn2b, bn2m, bn2v);      // 7

    k_head<<<1, 64>>>(l1W, l1b, l2W, l2b, out);                      // 8
}

// round 8
// speedup vs baseline: 1.0944x; 1.0944x over previous
#include <cuda_runtime.h>
#include <cuda_fp16.h>

#define NN 100000
#define EE 1000000
#define HH 64
#define GG 64
#define BN_EPS 1e-5f

// ---------------- scratch (static __device__, no allocations) ----------------
__device__ int      g_deg[NN];        // in-degree (excluding self loop)
__device__ int      g_off[NN];        // CSR offsets; after scatter: END offsets
__device__ int      g_csr[EE];        // CSR src row per incoming edge, bucketed by dst
__device__ float    g_dinv[NN];       // rsqrt(deg+1)
__device__ __half2  g_hs[NN * 32];    // transformed+scaled features (fp16)
__device__ float2   g_buf[NN * 32];   // layer-1 output (fp32, gemm2 input)
__device__ float    g_pool[GG * 64];  // pooled sums
__device__ int      g_gstart[GG + 1]; // graph segment starts
__device__ int      g_bsum[64];       // scan block sums
__device__ unsigned g_wfrag[2][2048]; // preformatted W fragments (half2 words), both layers

// ---------------- init: zero counters/pool, graph bounds, W fragment preformat ----------------
__global__ void k_zero(const int* __restrict__ batch,
                       const float* __restrict__ W1, const float* __restrict__ W2) {
    int i = blockIdx.x * blockDim.x + threadIdx.x;
    if (i < NN) g_deg[i] = 0;
    if (i < GG * 64) g_pool[i] = 0.f;
    if (i < 4096) {
        int l = i >> 11;
        int o = i & 2047;
        const float* W = l ? W2 : W1;
        int reg = o & 1, lane = (o >> 1) & 31, nt = (o >> 6) & 7, ktp = o >> 9;
        int n = nt * 8 + (lane >> 2);
        int k = ktp * 16 + reg * 8 + (lane & 3) * 2;
        __half2 h = __floats2half2_rn(W[n * 64 + k], W[n * 64 + k + 1]);
        g_wfrag[l][o] = *(unsigned*)&h;
    }
    if (i <= NN) {
        int prev = (i == 0) ? -1 : batch[i - 1];
        int cur  = (i < NN) ? batch[i] : GG;
        for (int g = prev + 1; g <= cur && g <= GG; g++) g_gstart[g] = i;
    }
}

// ---------------- degree histogram (4 edges/thread) ----------------
__global__ void k_degree(const int* __restrict__ ei) {
    int e = blockIdx.x * blockDim.x + threadIdx.x;
    if (e >= EE / 4) return;
    int4 c = ((const int4*)(ei + EE))[e];
    atomicAdd(&g_deg[c.x], 1);
    atomicAdd(&g_deg[c.y], 1);
    atomicAdd(&g_deg[c.z], 1);
    atomicAdd(&g_deg[c.w], 1);
}

// ---------------- scan stage A ----------------
__global__ void k_scan_a() {
    __shared__ int sh[256];
    int t = threadIdx.x;
    int base = blockIdx.x * 2048 + t * 8;
    int vals[8];
    int ts = 0;
#pragma unroll
    for (int j = 0; j < 8; j++) {
        int idx = base + j;
        vals[j] = (idx < NN) ? g_deg[idx] : 0;
        if (idx < NN) g_dinv[idx] = rsqrtf((float)(vals[j] + 1));
        ts += vals[j];
    }
    sh[t] = ts;
    __syncthreads();
#pragma unroll
    for (int d = 1; d < 256; d <<= 1) {
        int v = (t >= d) ? sh[t - d] : 0;
        __syncthreads();
        sh[t] += v;
        __syncthreads();
    }
    int excl = sh[t] - ts;
    int run = 0;
#pragma unroll
    for (int j = 0; j < 8; j++) {
        int idx = base + j;
        if (idx < NN) g_off[idx] = excl + run;
        run += vals[j];
    }
    if (t == 255) g_bsum[blockIdx.x] = sh[255];
}

// ---------------- scan stage C ----------------
__global__ void k_scan_c() {
    __shared__ int sv[64];
    __shared__ int pre;
    int t = threadIdx.x;
    int c = blockIdx.x >> 3;
    if (t < 64) sv[t] = (t < c) ? g_bsum[t] : 0;
    __syncthreads();
    if (t < 32) {
        int v = sv[t] + sv[t + 32];
#pragma unroll
        for (int d = 16; d > 0; d >>= 1) v += __shfl_down_sync(0xFFFFFFFFu, v, d);
        if (t == 0) pre = v;
    }
    __syncthreads();
    int i = blockIdx.x * 256 + t;
    if (i < NN) g_off[i] += pre;
}

// ---------------- CSR scatter (4 edges/thread) ----------------
__global__ void k_scatter(const int* __restrict__ ei) {
    int e = blockIdx.x * blockDim.x + threadIdx.x;
    if (e >= EE / 4) return;
    int4 r = ((const int4*)ei)[e];
    int4 c = ((const int4*)(ei + EE))[e];
    g_csr[atomicAdd(&g_off[c.x], 1)] = r.x;
    g_csr[atomicAdd(&g_off[c.y], 1)] = r.y;
    g_csr[atomicAdd(&g_off[c.z], 1)] = r.z;
    g_csr[atomicAdd(&g_off[c.w], 1)] = r.w;
}

// ---------------- GEMM via mma.sync m16n8k16 fp16 (fp32 accum) ----------------
// hs[v,:] = fp16( (X[v,:] @ W^T) * dinv[v] )
// Block: 256 thr / 8 warps / 128 rows. Warp w does rows [base+16w, base+16w+16).
__global__ void __launch_bounds__(256) k_gemm_mma(
    const float4* __restrict__ X4, const unsigned* __restrict__ wfrag,
    __half2* __restrict__ O) {
    __shared__ unsigned sA[8][4][32][4];   // 16KB: [warp][ktp][lane][reg]
    __shared__ unsigned sB[2048];          // 8KB
    int tid = threadIdx.x;
    int base = blockIdx.x * 128;

    // stage B: coalesced copy of preformatted fragments (once per 128 rows)
#pragma unroll
    for (int i = tid; i < 512; i += 256)
        ((uint4*)sB)[i] = ((const uint4*)wfrag)[i];

    // stage A: X rows -> fp16 fragments
    for (int i = tid; i < 2048; i += 256) {
        int r = i >> 4, j = i & 15;
        int R = base + r;
        float4 v = make_float4(0.f, 0.f, 0.f, 0.f);
        if (R < NN) v = X4[(size_t)R * 16 + j];
        int w8 = r >> 4, rr = r & 15;
        int ktp = j >> 2, jj = j & 3;
        int reg = ((rr >> 3) & 1) | ((jj >> 1) << 1);
        int t0 = (2 * jj) & 3;
        int lb = (rr & 7) * 4;
        __half2 h0 = __floats2half2_rn(v.x, v.y);
        __half2 h1 = __floats2half2_rn(v.z, v.w);
        sA[w8][ktp][lb + t0][reg]     = *(unsigned*)&h0;
        sA[w8][ktp][lb + t0 + 1][reg] = *(unsigned*)&h1;
    }
    __syncthreads();

    int lane = tid & 31;
    int w = tid >> 5;
    float d[8][4];
#pragma unroll
    for (int nt = 0; nt < 8; nt++)
#pragma unroll
        for (int j = 0; j < 4; j++) d[nt][j] = 0.f;

#pragma unroll
    for (int ktp = 0; ktp < 4; ktp++) {
        uint4 a = *(const uint4*)&sA[w][ktp][lane][0];  // LDS.128
#pragma unroll
        for (int nt = 0; nt < 8; nt++) {
            uint2 b = *(const uint2*)&sB[(((ktp << 3) + nt) << 6) + (lane << 1)];  // LDS.64
            asm volatile(
                "mma.sync.aligned.m16n8k16.row.col.f32.f16.f16.f32 "
                "{%0,%1,%2,%3}, {%4,%5,%6,%7}, {%8,%9}, {%0,%1,%2,%3};"
                : "+f"(d[nt][0]), "+f"(d[nt][1]), "+f"(d[nt][2]), "+f"(d[nt][3])
                : "r"(a.x), "r"(a.y), "r"(a.z), "r"(a.w), "r"(b.x), "r"(b.y));
        }
    }

    // epilogue: c0,c1 -> (row g, cols 2t..2t+1); c2,c3 -> (row g+8)
    int g = lane >> 2, t4 = lane & 3;
    int row0 = base + w * 16 + g;
    int row1 = row0 + 8;
    bool v0 = row0 < NN, v1 = row1 < NN;
    float dv0 = v0 ? g_dinv[row0] : 0.f;
    float dv1 = v1 ? g_dinv[row1] : 0.f;
#pragma unroll
    for (int nt = 0; nt < 8; nt++) {
        int cp = nt * 4 + t4;  // half2 column index
        if (v0) O[(size_t)row0 * 32 + cp] = __floats2half2_rn(d[nt][0] * dv0, d[nt][1] * dv0);
        if (v1) O[(size_t)row1 * 32 + cp] = __floats2half2_rn(d[nt][2] * dv1, d[nt][3] * dv1);
    }
}

// ---------------- aggregation + bias + BN + ReLU; optional fused pooling ----------------
// warp per node; lane l owns channels (2l, 2l+1)
template <bool POOL, int NODES_PER_BLK>
__global__ void k_agg(const __half2* __restrict__ hs, float2* __restrict__ out,
                      const int* __restrict__ batch,
                      const float* __restrict__ bias,
                      const float* __restrict__ bng, const float* __restrict__ bnb,
                      const float* __restrict__ bnm, const float* __restrict__ bnv) {
    __shared__ float sp[2][64];
    int t = threadIdx.x;
    int w0 = blockIdx.x * NODES_PER_BLK;
    int gid0 = 0, gidL = 0;
    if (POOL) {
        if (t < 128) sp[t >> 6][t & 63] = 0.f;
        gid0 = batch[w0];
        int wl = w0 + NODES_PER_BLK - 1;
        gidL = batch[wl < NN ? wl : NN - 1];
        __syncthreads();
    }
    int w = w0 + (t >> 5);
    int l = t & 31;
    float2 acc = make_float2(0.f, 0.f);
    if (w < NN) {
        float2 f = __half22float2(hs[(size_t)w * 32 + l]);  // self loop
        acc = f;
        int e = g_off[w];
        int cnt = g_deg[w];
        int s = e - cnt;
        int i = 0;
        for (; i + 4 <= cnt; i += 4) {
            int r0 = g_csr[s + i + 0];
            int r1 = g_csr[s + i + 1];
            int r2 = g_csr[s + i + 2];
            int r3 = g_csr[s + i + 3];
            float2 a0 = __half22float2(hs[(size_t)r0 * 32 + l]);
            float2 a1 = __half22float2(hs[(size_t)r1 * 32 + l]);
            float2 a2 = __half22float2(hs[(size_t)r2 * 32 + l]);
            float2 a3 = __half22float2(hs[(size_t)r3 * 32 + l]);
            acc.x += (a0.x + a1.x) + (a2.x + a3.x);
            acc.y += (a0.y + a1.y) + (a2.y + a3.y);
        }
        for (; i < cnt; i++) {
            float2 a = __half22float2(hs[(size_t)g_csr[s + i] * 32 + l]);
            acc.x += a.x;
            acc.y += a.y;
        }
        float dv = g_dinv[w];
        int c = 2 * l;
        float px = fmaf(acc.x, dv, bias[c]);
        float py = fmaf(acc.y, dv, bias[c + 1]);
        float sx = bng[c] * rsqrtf(bnv[c] + BN_EPS);
        float sy = bng[c + 1] * rsqrtf(bnv[c + 1] + BN_EPS);
        acc.x = fmaxf(0.f, fmaf(px - bnm[c], sx, bnb[c]));
        acc.y = fmaxf(0.f, fmaf(py - bnm[c + 1], sy, bnb[c + 1]));
        if (!POOL) {
            out[(size_t)w * 32 + l] = acc;
        } else {
            int gid = batch[w];
            int slot = gid - gid0;
            int c2 = 2 * l;
            if (slot < 2) {
                atomicAdd(&sp[slot][c2], acc.x);
                atomicAdd(&sp[slot][c2 + 1], acc.y);
            } else {
                atomicAdd(&g_pool[gid * 64 + c2], acc.x);
                atomicAdd(&g_pool[gid * 64 + c2 + 1], acc.y);
            }
        }
    }
    if (POOL) {
        __syncthreads();
        if (t < 128) {
            int s = t >> 6, ch = t & 63;
            int gg = gid0 + s;
            if (gg <= gidL && gg < GG) atomicAdd(&g_pool[gg * 64 + ch], sp[s][ch]);
        }
    }
}

// ---------------- MLP head ----------------
__global__ void k_head(const float* __restrict__ l1W, const float* __restrict__ l1b,
                       const float* __restrict__ l2W, const float* __restrict__ l2b,
                       float* __restrict__ out) {
    __shared__ float sW1[32 * 64];
    __shared__ float sW2[32];
    __shared__ float sB1[32];
    int t = threadIdx.x;  // 64 threads
    for (int i = t; i < 2048; i += 64) sW1[i] = l1W[i];
    if (t < 32) { sW2[t] = l2W[t]; sB1[t] = l1b[t]; }
    __syncthreads();
    if (t >= GG) return;
    int g = t;
    int cnt = g_gstart[g + 1] - g_gstart[g];
    float inv = 1.f / fmaxf((float)cnt, 1.f);
    float p[64];
#pragma unroll
    for (int k = 0; k < 64; k++) p[k] = g_pool[g * 64 + k] * inv;
    float o = l2b[0];
#pragma unroll 4
    for (int j = 0; j < 32; j++) {
        float hsum = sB1[j];
#pragma unroll
        for (int k = 0; k < 64; k++) hsum = fmaf(p[k], sW1[j * 64 + k], hsum);
        o = fmaf(fmaxf(hsum, 0.f), sW2[j], o);
    }
    out[g] = o;
}

// ---------------- launch ----------------
extern "C" void kernel_launch(void* const* d_in, const int* in_sizes, int n_in,
                              void* d_out, int out_size) {
    const float* x      = (const float*)d_in[0];
    const int*   ei     = (const int*)d_in[1];
    const int*   batch  = (const int*)d_in[2];
    const float* W1     = (const float*)d_in[3];
    const float* b1     = (const float*)d_in[4];
    const float* W2     = (const float*)d_in[5];
    const float* b2     = (const float*)d_in[6];
    const float* bn1g   = (const float*)d_in[7];
    const float* bn1b   = (const float*)d_in[8];
    const float* bn1m   = (const float*)d_in[9];
    const float* bn1v   = (const float*)d_in[10];
    const float* bn2g   = (const float*)d_in[11];
    const float* bn2b   = (const float*)d_in[12];
    const float* bn2m   = (const float*)d_in[13];
    const float* bn2v   = (const float*)d_in[14];
    const float* l1W    = (const float*)d_in[15];
    const float* l1b    = (const float*)d_in[16];
    const float* l2W    = (const float*)d_in[17];
    const float* l2b    = (const float*)d_in[18];
    float* out = (float*)d_out;

    __half2* hs;
    float2* buf;
    unsigned* wfrag;
    cudaGetSymbolAddress((void**)&hs, g_hs);
    cudaGetSymbolAddress((void**)&buf, g_buf);
    cudaGetSymbolAddress((void**)&wfrag, g_wfrag);

    const int TB = 256;
    int nb_e4 = (EE / 4 + TB - 1) / TB;
    int nb_scan = (NN + 2047) / 2048;   // 49
    int nb_gemm = (NN + 127) / 128;     // 782

    k_zero<<<(NN + 1 + TB - 1) / TB, TB>>>(batch, W1, W2);          // 0
    k_degree<<<nb_e4, TB>>>(ei);                                     // 1
    k_scan_a<<<nb_scan, 256>>>();                                    // 2
    k_gemm_mma<<<nb_gemm, 256>>>((const float4*)x, wfrag, hs);       // 3  <- ncu capture
    k_scan_c<<<(NN + 255) / 256, 256>>>();                           // 4
    k_scatter<<<nb_e4, TB>>>(ei);                                    // 5

    // layer 1: agg -> fp32 buf
    k_agg<false, 8><<<(NN + 7) / 8, 256>>>(hs, buf, batch, b1, bn1g, bn1b, bn1m, bn1v);      // 6
    // layer 2: transform
    k_gemm_mma<<<nb_gemm, 256>>>((const float4*)buf, wfrag + 2048, hs);                      // 7
    // layer 2: agg + fused pooling
    k_agg<true, 16><<<NN / 16, 512>>>(hs, nullptr, batch, b2, bn2g, bn2b, bn2m, bn2v);       // 8

    k_head<<<1, 64>>>(l1W, l1b, l2W, l2b, out);                      // 9
}

// round 9
// speedup vs baseline: 1.1142x; 1.0181x over previous
#include <cuda_runtime.h>
#include <cuda_fp16.h>

#define NN 100000
#define EE 1000000
#define HH 64
#define GG 64
#define BN_EPS 1e-5f

// ---------------- scratch (static __device__, no allocations) ----------------
__device__ int      g_deg[NN];        // in-degree (excluding self loop)
__device__ int      g_off[NN];        // CSR offsets; after scatter: END offsets
__device__ int      g_csr[EE];        // CSR src row per incoming edge, bucketed by dst
__device__ float    g_dinv[NN];       // rsqrt(deg+1)
__device__ __half2  g_hs[NN * 32];    // gemm output (fp16, 128B/row)
__device__ __half2  g_hb[NN * 32];    // agg1 output (fp16, gemm2 input)
__device__ float    g_pool[GG * 64];  // pooled sums
__device__ int      g_gstart[GG + 1]; // graph segment starts
__device__ int      g_bsum[64];       // scan block sums
__device__ unsigned g_wfrag[2][2048]; // preformatted W fragments (half2 words), both layers

// ---------------- init: zero counters/pool, graph bounds, W fragment preformat ----------------
__global__ void k_zero(const int* __restrict__ batch,
                       const float* __restrict__ W1, const float* __restrict__ W2) {
    int i = blockIdx.x * blockDim.x + threadIdx.x;
    if (i < NN) g_deg[i] = 0;
    if (i < GG * 64) g_pool[i] = 0.f;
    if (i < 4096) {
        int l = i >> 11;
        int o = i & 2047;
        const float* W = l ? W2 : W1;
        int reg = o & 1, lane = (o >> 1) & 31, nt = (o >> 6) & 7, ktp = o >> 9;
        int n = nt * 8 + (lane >> 2);
        int k = ktp * 16 + reg * 8 + (lane & 3) * 2;
        __half2 h = __floats2half2_rn(W[n * 64 + k], W[n * 64 + k + 1]);
        g_wfrag[l][o] = *(unsigned*)&h;
    }
    if (i <= NN) {
        int prev = (i == 0) ? -1 : batch[i - 1];
        int cur  = (i < NN) ? batch[i] : GG;
        for (int g = prev + 1; g <= cur && g <= GG; g++) g_gstart[g] = i;
    }
}

// ---------------- degree histogram (4 edges/thread) ----------------
__global__ void k_degree(const int* __restrict__ ei) {
    int e = blockIdx.x * blockDim.x + threadIdx.x;
    if (e >= EE / 4) return;
    int4 c = ((const int4*)(ei + EE))[e];
    atomicAdd(&g_deg[c.x], 1);
    atomicAdd(&g_deg[c.y], 1);
    atomicAdd(&g_deg[c.z], 1);
    atomicAdd(&g_deg[c.w], 1);
}

// ---------------- scan stage A ----------------
__global__ void k_scan_a() {
    __shared__ int sh[256];
    int t = threadIdx.x;
    int base = blockIdx.x * 2048 + t * 8;
    int vals[8];
    int ts = 0;
#pragma unroll
    for (int j = 0; j < 8; j++) {
        int idx = base + j;
        vals[j] = (idx < NN) ? g_deg[idx] : 0;
        if (idx < NN) g_dinv[idx] = rsqrtf((float)(vals[j] + 1));
        ts += vals[j];
    }
    sh[t] = ts;
    __syncthreads();
#pragma unroll
    for (int d = 1; d < 256; d <<= 1) {
        int v = (t >= d) ? sh[t - d] : 0;
        __syncthreads();
        sh[t] += v;
        __syncthreads();
    }
    int excl = sh[t] - ts;
    int run = 0;
#pragma unroll
    for (int j = 0; j < 8; j++) {
        int idx = base + j;
        if (idx < NN) g_off[idx] = excl + run;
        run += vals[j];
    }
    if (t == 255) g_bsum[blockIdx.x] = sh[255];
}

// ---------------- scan stage C ----------------
__global__ void k_scan_c() {
    __shared__ int sv[64];
    __shared__ int pre;
    int t = threadIdx.x;
    int c = blockIdx.x >> 3;
    if (t < 64) sv[t] = (t < c) ? g_bsum[t] : 0;
    __syncthreads();
    if (t < 32) {
        int v = sv[t] + sv[t + 32];
#pragma unroll
        for (int d = 16; d > 0; d >>= 1) v += __shfl_down_sync(0xFFFFFFFFu, v, d);
        if (t == 0) pre = v;
    }
    __syncthreads();
    int i = blockIdx.x * 256 + t;
    if (i < NN) g_off[i] += pre;
}

// ---------------- CSR scatter (4 edges/thread) ----------------
__global__ void k_scatter(const int* __restrict__ ei) {
    int e = blockIdx.x * blockDim.x + threadIdx.x;
    if (e >= EE / 4) return;
    int4 r = ((const int4*)ei)[e];
    int4 c = ((const int4*)(ei + EE))[e];
    g_csr[atomicAdd(&g_off[c.x], 1)] = r.x;
    g_csr[atomicAdd(&g_off[c.y], 1)] = r.y;
    g_csr[atomicAdd(&g_off[c.z], 1)] = r.z;
    g_csr[atomicAdd(&g_off[c.w], 1)] = r.w;
}

// ---------------- GEMM via mma.sync m16n8k16 fp16 (fp32 accum) ----------------
// hs[v,:] = fp16( (in[v,:] @ W^T) * dinv[v] ), input fp32 or fp16
// Block: 256 thr / 8 warps / 128 rows. Warp w does rows [base+16w, base+16w+16).
template <bool FP16IN>
__global__ void __launch_bounds__(256) k_gemm_mma(
    const void* __restrict__ Xin, const unsigned* __restrict__ wfrag,
    __half2* __restrict__ O) {
    __shared__ unsigned sA[8][4][32][4];   // 16KB: [warp][ktp][lane][reg]
    __shared__ unsigned sB[2048];          // 8KB
    int tid = threadIdx.x;
    int base = blockIdx.x * 128;

    // stage B: coalesced copy of preformatted fragments
#pragma unroll
    for (int i = tid; i < 512; i += 256)
        ((uint4*)sB)[i] = ((const uint4*)wfrag)[i];

    if (FP16IN) {
        // input row = 8 uint4 (8 halves each); no conversion, pure permutation
        const uint4* X = (const uint4*)Xin;
        for (int i = tid; i < 1024; i += 256) {
            int r = i >> 3, j = i & 7;
            int R = base + r;
            uint4 v = make_uint4(0u, 0u, 0u, 0u);
            if (R < NN) v = X[(size_t)R * 8 + j];
            int w8 = r >> 4, rr = r & 15;
            int ktp = j >> 1;
            int reg = ((rr >> 3) & 1) | ((j & 1) << 1);
            int lb = (rr & 7) * 4;
            sA[w8][ktp][lb + 0][reg] = v.x;
            sA[w8][ktp][lb + 1][reg] = v.y;
            sA[w8][ktp][lb + 2][reg] = v.z;
            sA[w8][ktp][lb + 3][reg] = v.w;
        }
    } else {
        const float4* X = (const float4*)Xin;
        for (int i = tid; i < 2048; i += 256) {
            int r = i >> 4, j = i & 15;
            int R = base + r;
            float4 v = make_float4(0.f, 0.f, 0.f, 0.f);
            if (R < NN) v = X[(size_t)R * 16 + j];
            int w8 = r >> 4, rr = r & 15;
            int ktp = j >> 2, jj = j & 3;
            int reg = ((rr >> 3) & 1) | ((jj >> 1) << 1);
            int t0 = (2 * jj) & 3;
            int lb = (rr & 7) * 4;
            __half2 h0 = __floats2half2_rn(v.x, v.y);
            __half2 h1 = __floats2half2_rn(v.z, v.w);
            sA[w8][ktp][lb + t0][reg]     = *(unsigned*)&h0;
            sA[w8][ktp][lb + t0 + 1][reg] = *(unsigned*)&h1;
        }
    }
    __syncthreads();

    int lane = tid & 31;
    int w = tid >> 5;
    float d[8][4];
#pragma unroll
    for (int nt = 0; nt < 8; nt++)
#pragma unroll
        for (int j = 0; j < 4; j++) d[nt][j] = 0.f;

#pragma unroll
    for (int ktp = 0; ktp < 4; ktp++) {
        uint4 a = *(const uint4*)&sA[w][ktp][lane][0];  // LDS.128
#pragma unroll
        for (int nt = 0; nt < 8; nt++) {
            uint2 b = *(const uint2*)&sB[(((ktp << 3) + nt) << 6) + (lane << 1)];  // LDS.64
            asm volatile(
                "mma.sync.aligned.m16n8k16.row.col.f32.f16.f16.f32 "
                "{%0,%1,%2,%3}, {%4,%5,%6,%7}, {%8,%9}, {%0,%1,%2,%3};"
                : "+f"(d[nt][0]), "+f"(d[nt][1]), "+f"(d[nt][2]), "+f"(d[nt][3])
                : "r"(a.x), "r"(a.y), "r"(a.z), "r"(a.w), "r"(b.x), "r"(b.y));
        }
    }

    int g = lane >> 2, t4 = lane & 3;
    int row0 = base + w * 16 + g;
    int row1 = row0 + 8;
    bool v0 = row0 < NN, v1 = row1 < NN;
    float dv0 = v0 ? g_dinv[row0] : 0.f;
    float dv1 = v1 ? g_dinv[row1] : 0.f;
#pragma unroll
    for (int nt = 0; nt < 8; nt++) {
        int cp = nt * 4 + t4;
        if (v0) O[(size_t)row0 * 32 + cp] = __floats2half2_rn(d[nt][0] * dv0, d[nt][1] * dv0);
        if (v1) O[(size_t)row1 * 32 + cp] = __floats2half2_rn(d[nt][2] * dv1, d[nt][3] * dv1);
    }
}

// ---------------- aggregation + bias + BN + ReLU; fp16 out OR fused pooling ----------------
// warp per node; lane l owns channels (2l, 2l+1)
template <bool POOL, int NODES_PER_BLK>
__global__ void k_agg(const __half2* __restrict__ hs, __half2* __restrict__ out,
                      const int* __restrict__ batch,
                      const float* __restrict__ bias,
                      const float* __restrict__ bng, const float* __restrict__ bnb,
                      const float* __restrict__ bnm, const float* __restrict__ bnv) {
    __shared__ float sp[2][64];
    int t = threadIdx.x;
    int w0 = blockIdx.x * NODES_PER_BLK;
    int gid0 = 0, gidL = 0;
    if (POOL) {
        if (t < 128) sp[t >> 6][t & 63] = 0.f;
        gid0 = batch[w0];
        int wl = w0 + NODES_PER_BLK - 1;
        gidL = batch[wl < NN ? wl : NN - 1];
        __syncthreads();
    }
    int w = w0 + (t >> 5);
    int l = t & 31;
    if (w < NN) {
        float2 acc = __half22float2(hs[(size_t)w * 32 + l]);  // self loop
        int e = g_off[w];
        int cnt = g_deg[w];
        int s = e - cnt;
        int i = 0;
        for (; i + 4 <= cnt; i += 4) {
            int r0 = g_csr[s + i + 0];
            int r1 = g_csr[s + i + 1];
            int r2 = g_csr[s + i + 2];
            int r3 = g_csr[s + i + 3];
            float2 a0 = __half22float2(hs[(size_t)r0 * 32 + l]);
            float2 a1 = __half22float2(hs[(size_t)r1 * 32 + l]);
            float2 a2 = __half22float2(hs[(size_t)r2 * 32 + l]);
            float2 a3 = __half22float2(hs[(size_t)r3 * 32 + l]);
            acc.x += (a0.x + a1.x) + (a2.x + a3.x);
            acc.y += (a0.y + a1.y) + (a2.y + a3.y);
        }
        for (; i < cnt; i++) {
            float2 a = __half22float2(hs[(size_t)g_csr[s + i] * 32 + l]);
            acc.x += a.x;
            acc.y += a.y;
        }
        float dv = g_dinv[w];
        int c = 2 * l;
        float px = fmaf(acc.x, dv, bias[c]);
        float py = fmaf(acc.y, dv, bias[c + 1]);
        float sx = bng[c] * rsqrtf(bnv[c] + BN_EPS);
        float sy = bng[c + 1] * rsqrtf(bnv[c + 1] + BN_EPS);
        float ox = fmaxf(0.f, fmaf(px - bnm[c], sx, bnb[c]));
        float oy = fmaxf(0.f, fmaf(py - bnm[c + 1], sy, bnb[c + 1]));
        if (!POOL) {
            out[(size_t)w * 32 + l] = __floats2half2_rn(ox, oy);
        } else {
            int gid = batch[w];
            int slot = gid - gid0;
            if (slot < 2) {
                atomicAdd(&sp[slot][c], ox);
                atomicAdd(&sp[slot][c + 1], oy);
            } else {
                atomicAdd(&g_pool[gid * 64 + c], ox);
                atomicAdd(&g_pool[gid * 64 + c + 1], oy);
            }
        }
    }
    if (POOL) {
        __syncthreads();
        if (t < 128) {
            int s = t >> 6, ch = t & 63;
            int gg = gid0 + s;
            if (gg <= gidL && gg < GG) atomicAdd(&g_pool[gg * 64 + ch], sp[s][ch]);
        }
    }
}

// ---------------- MLP head ----------------
__global__ void k_head(const float* __restrict__ l1W, const float* __restrict__ l1b,
                       const float* __restrict__ l2W, const float* __restrict__ l2b,
                       float* __restrict__ out) {
    __shared__ float sW1[32 * 64];
    __shared__ float sW2[32];
    __shared__ float sB1[32];
    int t = threadIdx.x;  // 64 threads
    for (int i = t; i < 2048; i += 64) sW1[i] = l1W[i];
    if (t < 32) { sW2[t] = l2W[t]; sB1[t] = l1b[t]; }
    __syncthreads();
    if (t >= GG) return;
    int g = t;
    int cnt = g_gstart[g + 1] - g_gstart[g];
    float inv = 1.f / fmaxf((float)cnt, 1.f);
    float p[64];
#pragma unroll
    for (int k = 0; k < 64; k++) p[k] = g_pool[g * 64 + k] * inv;
    float o = l2b[0];
#pragma unroll 4
    for (int j = 0; j < 32; j++) {
        float hsum = sB1[j];
#pragma unroll
        for (int k = 0; k < 64; k++) hsum = fmaf(p[k], sW1[j * 64 + k], hsum);
        o = fmaf(fmaxf(hsum, 0.f), sW2[j], o);
    }
    out[g] = o;
}

// ---------------- launch ----------------
extern "C" void kernel_launch(void* const* d_in, const int* in_sizes, int n_in,
                              void* d_out, int out_size) {
    const float* x      = (const float*)d_in[0];
    const int*   ei     = (const int*)d_in[1];
    const int*   batch  = (const int*)d_in[2];
    const float* W1     = (const float*)d_in[3];
    const float* b1     = (const float*)d_in[4];
    const float* W2     = (const float*)d_in[5];
    const float* b2     = (const float*)d_in[6];
    const float* bn1g   = (const float*)d_in[7];
    const float* bn1b   = (const float*)d_in[8];
    const float* bn1m   = (const float*)d_in[9];
    const float* bn1v   = (const float*)d_in[10];
    const float* bn2g   = (const float*)d_in[11];
    const float* bn2b   = (const float*)d_in[12];
    const float* bn2m   = (const float*)d_in[13];
    const float* bn2v   = (const float*)d_in[14];
    const float* l1W    = (const float*)d_in[15];
    const float* l1b    = (const float*)d_in[16];
    const float* l2W    = (const float*)d_in[17];
    const float* l2b    = (const float*)d_in[18];
    float* out = (float*)d_out;

    __half2 *hs, *hb;
    unsigned* wfrag;
    cudaGetSymbolAddress((void**)&hs, g_hs);
    cudaGetSymbolAddress((void**)&hb, g_hb);
    cudaGetSymbolAddress((void**)&wfrag, g_wfrag);

    const int TB = 256;
    int nb_e4 = (EE / 4 + TB - 1) / TB;
    int nb_scan = (NN + 2047) / 2048;   // 49
    int nb_gemm = (NN + 127) / 128;     // 782

    k_zero<<<(NN + 1 + TB - 1) / TB, TB>>>(batch, W1, W2);              // 0
    k_degree<<<nb_e4, TB>>>(ei);                                         // 1
    k_scan_a<<<nb_scan, 256>>>();                                        // 2
    k_gemm_mma<false><<<nb_gemm, 256>>>(x, wfrag, hs);                   // 3  <- ncu capture
    k_scan_c<<<(NN + 255) / 256, 256>>>();                               // 4
    k_scatter<<<nb_e4, TB>>>(ei);                                        // 5

    // layer 1: agg -> fp16 hb
    k_agg<false, 8><<<(NN + 7) / 8, 256>>>(hs, hb, batch, b1, bn1g, bn1b, bn1m, bn1v);   // 6
    // layer 2: transform (fp16 input)
    k_gemm_mma<true><<<nb_gemm, 256>>>(hb, wfrag + 2048, hs);                            // 7
    // layer 2: agg + fused pooling
    k_agg<true, 16><<<NN / 16, 512>>>(hs, nullptr, batch, b2, bn2g, bn2b, bn2m, bn2v);   // 8

    k_head<<<1, 64>>>(l1W, l1b, l2W, l2b, out);                          // 9
}

// round 10
// speedup vs baseline: 1.1491x; 1.0313x over previous
#include <cuda_runtime.h>
#include <cuda_fp16.h>

#define NN 100000
#define EE 1000000
#define HH 64
#define GG 64
#define BN_EPS 1e-5f

// ---------------- scratch (static __device__, no allocations) ----------------
__device__ int      g_deg[NN];        // in-degree (excluding self loop)
__device__ int      g_off[NN];        // CSR offsets; after scatter: END offsets
__device__ int      g_csr[EE];        // CSR src row per incoming edge, bucketed by dst
__device__ float    g_dinv[NN];       // rsqrt(deg+1)
__device__ __half2  g_hs[NN * 32];    // gemm output (fp16, 128B/row)
__device__ __half2  g_hb[NN * 32];    // agg1 output (fp16, gemm2 input)
__device__ float    g_pool[GG * 64];  // pooled sums
__device__ int      g_gstart[GG + 1]; // graph segment starts
__device__ int      g_bsum[64];       // scan block sums
__device__ unsigned g_wfrag[2][2048]; // preformatted W fragments (half2 words), both layers

// ---------------- init: zero counters/pool, graph bounds, W fragment preformat ----------------
__global__ void k_zero(const int* __restrict__ batch,
                       const float* __restrict__ W1, const float* __restrict__ W2) {
    int i = blockIdx.x * blockDim.x + threadIdx.x;
    if (i < NN) g_deg[i] = 0;
    if (i < GG * 64) g_pool[i] = 0.f;
    if (i < 4096) {
        int l = i >> 11;
        int o = i & 2047;
        const float* W = l ? W2 : W1;
        int reg = o & 1, lane = (o >> 1) & 31, nt = (o >> 6) & 7, ktp = o >> 9;
        int n = nt * 8 + (lane >> 2);
        int k = ktp * 16 + reg * 8 + (lane & 3) * 2;
        __half2 h = __floats2half2_rn(W[n * 64 + k], W[n * 64 + k + 1]);
        g_wfrag[l][o] = *(unsigned*)&h;
    }
    if (i <= NN) {
        int prev = (i == 0) ? -1 : batch[i - 1];
        int cur  = (i < NN) ? batch[i] : GG;
        for (int g = prev + 1; g <= cur && g <= GG; g++) g_gstart[g] = i;
    }
}

// ---------------- degree histogram (4 edges/thread) ----------------
__global__ void k_degree(const int* __restrict__ ei) {
    int e = blockIdx.x * blockDim.x + threadIdx.x;
    if (e >= EE / 4) return;
    int4 c = ((const int4*)(ei + EE))[e];
    atomicAdd(&g_deg[c.x], 1);
    atomicAdd(&g_deg[c.y], 1);
    atomicAdd(&g_deg[c.z], 1);
    atomicAdd(&g_deg[c.w], 1);
}

// ---------------- scan stage A ----------------
__global__ void k_scan_a() {
    __shared__ int sh[256];
    int t = threadIdx.x;
    int base = blockIdx.x * 2048 + t * 8;
    int vals[8];
    int ts = 0;
#pragma unroll
    for (int j = 0; j < 8; j++) {
        int idx = base + j;
        vals[j] = (idx < NN) ? g_deg[idx] : 0;
        if (idx < NN) g_dinv[idx] = rsqrtf((float)(vals[j] + 1));
        ts += vals[j];
    }
    sh[t] = ts;
    __syncthreads();
#pragma unroll
    for (int d = 1; d < 256; d <<= 1) {
        int v = (t >= d) ? sh[t - d] : 0;
        __syncthreads();
        sh[t] += v;
        __syncthreads();
    }
    int excl = sh[t] - ts;
    int run = 0;
#pragma unroll
    for (int j = 0; j < 8; j++) {
        int idx = base + j;
        if (idx < NN) g_off[idx] = excl + run;
        run += vals[j];
    }
    if (t == 255) g_bsum[blockIdx.x] = sh[255];
}

// ---------------- scan stage C ----------------
__global__ void k_scan_c() {
    __shared__ int sv[64];
    __shared__ int pre;
    int t = threadIdx.x;
    int c = blockIdx.x >> 3;
    if (t < 64) sv[t] = (t < c) ? g_bsum[t] : 0;
    __syncthreads();
    if (t < 32) {
        int v = sv[t] + sv[t + 32];
#pragma unroll
        for (int d = 16; d > 0; d >>= 1) v += __shfl_down_sync(0xFFFFFFFFu, v, d);
        if (t == 0) pre = v;
    }
    __syncthreads();
    int i = blockIdx.x * 256 + t;
    if (i < NN) g_off[i] += pre;
}

// ---------------- CSR scatter (4 edges/thread) ----------------
__global__ void k_scatter(const int* __restrict__ ei) {
    int e = blockIdx.x * blockDim.x + threadIdx.x;
    if (e >= EE / 4) return;
    int4 r = ((const int4*)ei)[e];
    int4 c = ((const int4*)(ei + EE))[e];
    g_csr[atomicAdd(&g_off[c.x], 1)] = r.x;
    g_csr[atomicAdd(&g_off[c.y], 1)] = r.y;
    g_csr[atomicAdd(&g_off[c.z], 1)] = r.z;
    g_csr[atomicAdd(&g_off[c.w], 1)] = r.w;
}

// ---------------- GEMM via mma.sync m16n8k16 fp16 (fp32 accum) ----------------
// hs[v,:] = fp16( (in[v,:] @ W^T) * dinv[v] ), input fp32 or fp16
// Block: 256 thr / 8 warps / 128 rows. Coalesced epilogue via smem transpose.
template <bool FP16IN>
__global__ void __launch_bounds__(256) k_gemm_mma(
    const void* __restrict__ Xin, const unsigned* __restrict__ wfrag,
    __half2* __restrict__ O) {
    __shared__ unsigned shm[6144];  // 24KB: sA(4096) + sB(2048); reused as sD(128*36=4608)
    unsigned (*sA)[4][32][4] = (unsigned (*)[4][32][4])shm;
    unsigned* sB = shm + 4096;
    int tid = threadIdx.x;
    int base = blockIdx.x * 128;

    // stage B: coalesced copy of preformatted fragments
#pragma unroll
    for (int i = tid; i < 512; i += 256)
        ((uint4*)sB)[i] = ((const uint4*)wfrag)[i];

    if (FP16IN) {
        const uint4* X = (const uint4*)Xin;
        for (int i = tid; i < 1024; i += 256) {
            int r = i >> 3, j = i & 7;
            int R = base + r;
            uint4 v = make_uint4(0u, 0u, 0u, 0u);
            if (R < NN) v = X[(size_t)R * 8 + j];
            int w8 = r >> 4, rr = r & 15;
            int ktp = j >> 1;
            int reg = ((rr >> 3) & 1) | ((j & 1) << 1);
            int lb = (rr & 7) * 4;
            sA[w8][ktp][lb + 0][reg] = v.x;
            sA[w8][ktp][lb + 1][reg] = v.y;
            sA[w8][ktp][lb + 2][reg] = v.z;
            sA[w8][ktp][lb + 3][reg] = v.w;
        }
    } else {
        const float4* X = (const float4*)Xin;
        for (int i = tid; i < 2048; i += 256) {
            int r = i >> 4, j = i & 15;
            int R = base + r;
            float4 v = make_float4(0.f, 0.f, 0.f, 0.f);
            if (R < NN) v = X[(size_t)R * 16 + j];
            int w8 = r >> 4, rr = r & 15;
            int ktp = j >> 2, jj = j & 3;
            int reg = ((rr >> 3) & 1) | ((jj >> 1) << 1);
            int t0 = (2 * jj) & 3;
            int lb = (rr & 7) * 4;
            __half2 h0 = __floats2half2_rn(v.x, v.y);
            __half2 h1 = __floats2half2_rn(v.z, v.w);
            sA[w8][ktp][lb + t0][reg]     = *(unsigned*)&h0;
            sA[w8][ktp][lb + t0 + 1][reg] = *(unsigned*)&h1;
        }
    }
    __syncthreads();

    int lane = tid & 31;
    int w = tid >> 5;
    float d[8][4];
#pragma unroll
    for (int nt = 0; nt < 8; nt++)
#pragma unroll
        for (int j = 0; j < 4; j++) d[nt][j] = 0.f;

#pragma unroll
    for (int ktp = 0; ktp < 4; ktp++) {
        uint4 a = *(const uint4*)&sA[w][ktp][lane][0];  // LDS.128
#pragma unroll
        for (int nt = 0; nt < 8; nt++) {
            uint2 b = *(const uint2*)&sB[(((ktp << 3) + nt) << 6) + (lane << 1)];  // LDS.64
            asm volatile(
                "mma.sync.aligned.m16n8k16.row.col.f32.f16.f16.f32 "
                "{%0,%1,%2,%3}, {%4,%5,%6,%7}, {%8,%9}, {%0,%1,%2,%3};"
                : "+f"(d[nt][0]), "+f"(d[nt][1]), "+f"(d[nt][2]), "+f"(d[nt][3])
                : "r"(a.x), "r"(a.y), "r"(a.z), "r"(a.w), "r"(b.x), "r"(b.y));
        }
    }

    // epilogue stage 1: fragments -> smem (stride 36 words/row: conflict-free banks)
    __syncthreads();  // done reading sA/sB
    unsigned* sD = shm;
    int g = lane >> 2, t4 = lane & 3;
    int rl0 = w * 16 + g, rl1 = rl0 + 8;
    int row0 = base + rl0, row1 = base + rl1;
    float dv0 = (row0 < NN) ? g_dinv[row0] : 0.f;
    float dv1 = (row1 < NN) ? g_dinv[row1] : 0.f;
#pragma unroll
    for (int nt = 0; nt < 8; nt++) {
        int cp = nt * 4 + t4;
        __half2 h0 = __floats2half2_rn(d[nt][0] * dv0, d[nt][1] * dv0);
        __half2 h1 = __floats2half2_rn(d[nt][2] * dv1, d[nt][3] * dv1);
        sD[rl0 * 36 + cp] = *(unsigned*)&h0;
        sD[rl1 * 36 + cp] = *(unsigned*)&h1;
    }
    __syncthreads();

    // epilogue stage 2: coalesced STG.128 (4 uint4 per thread)
#pragma unroll
    for (int i = tid; i < 1024; i += 256) {
        int r = i >> 3, col = i & 7;
        int R = base + r;
        if (R < NN)
            ((uint4*)O)[(size_t)R * 8 + col] = *(const uint4*)&sD[r * 36 + col * 4];
    }
}

// ---------------- aggregation + bias + BN + ReLU; fp16 out OR fused pooling ----------------
// warp per node; lane l owns channels (2l, 2l+1)
template <bool POOL, int NODES_PER_BLK>
__global__ void k_agg(const __half2* __restrict__ hs, __half2* __restrict__ out,
                      const int* __restrict__ batch,
                      const float* __restrict__ bias,
                      const float* __restrict__ bng, const float* __restrict__ bnb,
                      const float* __restrict__ bnm, const float* __restrict__ bnv) {
    __shared__ float sp[2][64];
    int t = threadIdx.x;
    int w0 = blockIdx.x * NODES_PER_BLK;
    int gid0 = 0, gidL = 0;
    if (POOL) {
        if (t < 128) sp[t >> 6][t & 63] = 0.f;
        gid0 = batch[w0];
        int wl = w0 + NODES_PER_BLK - 1;
        gidL = batch[wl < NN ? wl : NN - 1];
        __syncthreads();
    }
    int w = w0 + (t >> 5);
    int l = t & 31;
    if (w < NN) {
        float2 acc = __half22float2(hs[(size_t)w * 32 + l]);  // self loop
        int e = g_off[w];
        int cnt = g_deg[w];
        int s = e - cnt;
        int i = 0;
        for (; i + 4 <= cnt; i += 4) {
            int r0 = g_csr[s + i + 0];
            int r1 = g_csr[s + i + 1];
            int r2 = g_csr[s + i + 2];
            int r3 = g_csr[s + i + 3];
            float2 a0 = __half22float2(hs[(size_t)r0 * 32 + l]);
            float2 a1 = __half22float2(hs[(size_t)r1 * 32 + l]);
            float2 a2 = __half22float2(hs[(size_t)r2 * 32 + l]);
            float2 a3 = __half22float2(hs[(size_t)r3 * 32 + l]);
            acc.x += (a0.x + a1.x) + (a2.x + a3.x);
            acc.y += (a0.y + a1.y) + (a2.y + a3.y);
        }
        for (; i < cnt; i++) {
            float2 a = __half22float2(hs[(size_t)g_csr[s + i] * 32 + l]);
            acc.x += a.x;
            acc.y += a.y;
        }
        float dv = g_dinv[w];
        int c = 2 * l;
        float px = fmaf(acc.x, dv, bias[c]);
        float py = fmaf(acc.y, dv, bias[c + 1]);
        float sx = bng[c] * rsqrtf(bnv[c] + BN_EPS);
        float sy = bng[c + 1] * rsqrtf(bnv[c + 1] + BN_EPS);
        float ox = fmaxf(0.f, fmaf(px - bnm[c], sx, bnb[c]));
        float oy = fmaxf(0.f, fmaf(py - bnm[c + 1], sy, bnb[c + 1]));
        if (!POOL) {
            out[(size_t)w * 32 + l] = __floats2half2_rn(ox, oy);
        } else {
            int gid = batch[w];
            int slot = gid - gid0;
            if (slot < 2) {
                atomicAdd(&sp[slot][c], ox);
                atomicAdd(&sp[slot][c + 1], oy);
            } else {
                atomicAdd(&g_pool[gid * 64 + c], ox);
                atomicAdd(&g_pool[gid * 64 + c + 1], oy);
            }
        }
    }
    if (POOL) {
        __syncthreads();
        if (t < 128) {
            int s = t >> 6, ch = t & 63;
            int gg = gid0 + s;
            if (gg <= gidL && gg < GG) atomicAdd(&g_pool[gg * 64 + ch], sp[s][ch]);
        }
    }
}

// ---------------- MLP head ----------------
__global__ void k_head(const float* __restrict__ l1W, const float* __restrict__ l1b,
                       const float* __restrict__ l2W, const float* __restrict__ l2b,
                       float* __restrict__ out) {
    __shared__ float sW1[32 * 64];
    __shared__ float sW2[32];
    __shared__ float sB1[32];
    int t = threadIdx.x;  // 64 threads
    for (int i = t; i < 2048; i += 64) sW1[i] = l1W[i];
    if (t < 32) { sW2[t] = l2W[t]; sB1[t] = l1b[t]; }
    __syncthreads();
    if (t >= GG) return;
    int g = t;
    int cnt = g_gstart[g + 1] - g_gstart[g];
    float inv = 1.f / fmaxf((float)cnt, 1.f);
    float p[64];
#pragma unroll
    for (int k = 0; k < 64; k++) p[k] = g_pool[g * 64 + k] * inv;
    float o = l2b[0];
#pragma unroll 4
    for (int j = 0; j < 32; j++) {
        float hsum = sB1[j];
#pragma unroll
        for (int k = 0; k < 64; k++) hsum = fmaf(p[k], sW1[j * 64 + k], hsum);
        o = fmaf(fmaxf(hsum, 0.f), sW2[j], o);
    }
    out[g] = o;
}

// ---------------- launch ----------------
extern "C" void kernel_launch(void* const* d_in, const int* in_sizes, int n_in,
                              void* d_out, int out_size) {
    const float* x      = (const float*)d_in[0];
    const int*   ei     = (const int*)d_in[1];
    const int*   batch  = (const int*)d_in[2];
    const float* W1     = (const float*)d_in[3];
    const float* b1     = (const float*)d_in[4];
    const float* W2     = (const float*)d_in[5];
    const float* b2     = (const float*)d_in[6];
    const float* bn1g   = (const float*)d_in[7];
    const float* bn1b   = (const float*)d_in[8];
    const float* bn1m   = (const float*)d_in[9];
    const float* bn1v   = (const float*)d_in[10];
    const float* bn2g   = (const float*)d_in[11];
    const float* bn2b   = (const float*)d_in[12];
    const float* bn2m   = (const float*)d_in[13];
    const float* bn2v   = (const float*)d_in[14];
    const float* l1W    = (const float*)d_in[15];
    const float* l1b    = (const float*)d_in[16];
    const float* l2W    = (const float*)d_in[17];
    const float* l2b    = (const float*)d_in[18];
    float* out = (float*)d_out;

    __half2 *hs, *hb;
    unsigned* wfrag;
    cudaGetSymbolAddress((void**)&hs, g_hs);
    cudaGetSymbolAddress((void**)&hb, g_hb);
    cudaGetSymbolAddress((void**)&wfrag, g_wfrag);

    const int TB = 256;
    int nb_e4 = (EE / 4 + TB - 1) / TB;
    int nb_scan = (NN + 2047) / 2048;   // 49
    int nb_gemm = (NN + 127) / 128;     // 782

    k_zero<<<(NN + 1 + TB - 1) / TB, TB>>>(batch, W1, W2);              // 0
    k_degree<<<nb_e4, TB>>>(ei);                                         // 1
    k_scan_a<<<nb_scan, 256>>>();                                        // 2
    k_gemm_mma<false><<<nb_gemm, 256>>>(x, wfrag, hs);                   // 3  <- ncu capture
    k_scan_c<<<(NN + 255) / 256, 256>>>();                               // 4
    k_scatter<<<nb_e4, TB>>>(ei);                                        // 5

    // layer 1: agg -> fp16 hb
    k_agg<false, 8><<<(NN + 7) / 8, 256>>>(hs, hb, batch, b1, bn1g, bn1b, bn1m, bn1v);   // 6
    // layer 2: transform (fp16 input)
    k_gemm_mma<true><<<nb_gemm, 256>>>(hb, wfrag + 2048, hs);                            // 7
    // layer 2: agg + fused pooling
    k_agg<true, 16><<<NN / 16, 512>>>(hs, nullptr, batch, b2, bn2g, bn2b, bn2m, bn2v);   // 8

    k_head<<<1, 64>>>(l1W, l1b, l2W, l2b, out);                          // 9
}